// round 5
// baseline (speedup 1.0000x reference)
#include <cuda_runtime.h>
#include <cuda_fp16.h>
#include <cstdint>

// VQ argmin: 32768 positions x 1024 codewords, C=256.
// inputs [32,256,32,32] f32, embed [256,1024] f32.
// out = concat(quantize_st [8388608], loss [1], onehot [33554432]) f32.
// Strategy: single fp16 HMMA GEMM for scores (error sigma ~0.009), exact fp32
// re-argmin repair for positions whose top-2 margin < 0.1 (~250 expected).

#define NPOS   32768
#define KEMB   1024
#define CDIM   256
#define QELEMS 8388608

// ---------------------------------------------------------------------------
// device scratch
// ---------------------------------------------------------------------------
__device__ __align__(256) __half g_Xh[NPOS * CDIM];
__device__ __align__(256) __half g_Eh[KEMB * CDIM];
__device__ float g_esqh[KEMB];
__device__ int   g_idx[NPOS];
__device__ float g_loss;
__device__ int   g_nrep;
__device__ int   g_rep[NPOS];
// per-(kblock, position) partial top-2
__device__ float g_p1[8 * NPOS];
__device__ float g_p2[8 * NPOS];
__device__ int   g_pk[8 * NPOS];

// ---------------------------------------------------------------------------
// helpers
// ---------------------------------------------------------------------------
__device__ __forceinline__ uint32_t s2u(const void* p) {
    uint32_t a;
    asm("{ .reg .u64 t; cvta.to.shared.u64 t, %1; cvt.u32.u64 %0, t; }" : "=r"(a) : "l"(p));
    return a;
}
__device__ __forceinline__ void cp16(uint32_t s, const void* g) {
    asm volatile("cp.async.cg.shared.global [%0], [%1], 16;" :: "r"(s), "l"(g));
}
__device__ __forceinline__ void cpcommit() { asm volatile("cp.async.commit_group;"); }
template <int N>
__device__ __forceinline__ void cpwait() { asm volatile("cp.async.wait_group %0;" :: "n"(N)); }

__device__ __forceinline__ void ldm_x4(uint32_t& r0, uint32_t& r1, uint32_t& r2, uint32_t& r3,
                                       uint32_t addr) {
    asm volatile("ldmatrix.sync.aligned.m8n8.x4.shared.b16 {%0,%1,%2,%3}, [%4];"
                 : "=r"(r0), "=r"(r1), "=r"(r2), "=r"(r3) : "r"(addr));
}
__device__ __forceinline__ void ldm_x2(uint32_t& r0, uint32_t& r1, uint32_t addr) {
    asm volatile("ldmatrix.sync.aligned.m8n8.x2.shared.b16 {%0,%1}, [%2];"
                 : "=r"(r0), "=r"(r1) : "r"(addr));
}
__device__ __forceinline__ void mma16816(float* d, const uint32_t* a, const uint32_t* b) {
    asm volatile(
        "mma.sync.aligned.m16n8k16.row.col.f32.f16.f16.f32 "
        "{%0,%1,%2,%3}, {%4,%5,%6,%7}, {%8,%9}, {%0,%1,%2,%3};"
        : "+f"(d[0]), "+f"(d[1]), "+f"(d[2]), "+f"(d[3])
        : "r"(a[0]), "r"(a[1]), "r"(a[2]), "r"(a[3]), "r"(b[0]), "r"(b[1]));
}

// ---------------------------------------------------------------------------
// Kernel: 0.5*||e_k||^2 + counter reset
// ---------------------------------------------------------------------------
__global__ void k_esq(const float* __restrict__ emb) {
    int k = blockIdx.x * 256 + threadIdx.x;
    float s = 0.f;
    #pragma unroll 8
    for (int c = 0; c < CDIM; ++c) {
        float e = emb[c * KEMB + k];
        s = fmaf(e, e, s);
    }
    g_esqh[k] = 0.5f * s;
    if (k == 0) { g_loss = 0.f; g_nrep = 0; }
}

// ---------------------------------------------------------------------------
// Kernel: transpose + fp16 convert ([256][1024] f32 slices -> [n][256] fp16)
// ---------------------------------------------------------------------------
__global__ void k_split(const float* __restrict__ src, int is_embed) {
    __half* __restrict__ dst = is_embed ? g_Eh : g_Xh;
    __shared__ float Xs[32][257];
    const int t = threadIdx.x;
    const int s = blockIdx.x >> 5;
    const int hw0 = (blockIdx.x & 31) * 32;
    const int lane = t & 31, w = t >> 5;
    const float* sp = src + (size_t)s * (CDIM * 1024);

    #pragma unroll
    for (int i = 0; i < 32; ++i) {
        int c = w + i * 8;
        Xs[lane][c] = sp[(size_t)c * 1024 + hw0 + lane];
    }
    __syncthreads();

    #pragma unroll
    for (int rr = 0; rr < 4; ++rr) {
        int r = w * 4 + rr;
        size_t ob = ((size_t)s * 1024 + hw0 + r) * CDIM;
        #pragma unroll
        for (int j = 0; j < 8; ++j) {
            int c = lane + 32 * j;
            dst[ob + c] = __float2half_rn(Xs[r][c]);
        }
    }
}

// ---------------------------------------------------------------------------
// Kernel: fp16 HMMA GEMM tile + per-row top-2.
// Grid 2048: nb = bid>>3 (128 positions), kb = bid&7 (128 codewords).
// C = 256 as 8 BK=32 chunks; 3-stage cp.async pipeline.
// 8 warps as 2(M) x 4(N); warp tile 64x32.
// ---------------------------------------------------------------------------
#define ROWB   80                 // smem bytes per row (40 halves, 16B-mult)
#define STG_A  (128 * ROWB)       // 10240
#define STG    (2 * STG_A)        // A+B per stage
#define NCHUNK 8
#define MMA_SMEM (3 * STG)        // 61440

__global__ __launch_bounds__(256, 2) void k_mma() {
    extern __shared__ char dsm[];
    const uint32_t sb = s2u(dsm);
    __shared__ float sEsq[128];
    __shared__ float sv1[4][128];
    __shared__ float sv2[4][128];
    __shared__ int   sk1[4][128];

    const int tid = threadIdx.x;
    const int l   = tid & 31;
    const int wid = tid >> 5;
    const int wm  = wid & 1;       // m-offset 64*wm
    const int wn  = wid >> 1;      // n-offset 32*wn

    const int nb = blockIdx.x >> 3;
    const int kb = blockIdx.x & 7;
    const int n0 = nb * 128;
    const int k0 = kb * 128;

    if (tid < 128) sEsq[tid] = g_esqh[k0 + tid];

    const __half* Ag0 = g_Xh + (size_t)n0 * CDIM;
    const __half* Bg0 = g_Eh + (size_t)k0 * CDIM;

    auto load_chunk = [&](int c, int s) {
        const __half* Ag = Ag0 + c * 32;
        const __half* Bg = Bg0 + c * 32;
        const uint32_t ab = sb + s * STG, bbs = ab + STG_A;
        #pragma unroll
        for (int u = 0; u < 2; ++u) {
            const int idx = tid + u * 256;        // 0..511
            const int row = idx >> 2, q = idx & 3;
            cp16(ab  + row * ROWB + q * 16, Ag + (size_t)row * CDIM + q * 8);
            cp16(bbs + row * ROWB + q * 16, Bg + (size_t)row * CDIM + q * 8);
        }
        cpcommit();
    };

    float acc[4][4][4];
    #pragma unroll
    for (int i = 0; i < 4; ++i)
        #pragma unroll
        for (int j = 0; j < 4; ++j)
            #pragma unroll
            for (int r = 0; r < 4; ++r) acc[i][j][r] = 0.f;

    load_chunk(0, 0);
    load_chunk(1, 1);
    load_chunk(2, 2);

    #pragma unroll 1
    for (int c = 0; c < NCHUNK; ++c) {
        if (c <= NCHUNK - 3)      cpwait<2>();
        else if (c == NCHUNK - 2) cpwait<1>();
        else                      cpwait<0>();
        __syncthreads();

        const int s = c % 3;
        const uint32_t ab = sb + s * STG, bbs = ab + STG_A;
        #pragma unroll
        for (int ks = 0; ks < 2; ++ks) {
            uint32_t afr[4][4], bfr[4][2];
            #pragma unroll
            for (int mt = 0; mt < 4; ++mt)
                ldm_x4(afr[mt][0], afr[mt][1], afr[mt][2], afr[mt][3],
                       ab + (uint32_t)(wm * 64 + mt * 16 + (l & 15)) * ROWB
                          + (uint32_t)(ks * 16 + (l >> 4) * 8) * 2);
            #pragma unroll
            for (int nt = 0; nt < 4; ++nt)
                ldm_x2(bfr[nt][0], bfr[nt][1],
                       bbs + (uint32_t)(wn * 32 + nt * 8 + (l & 7)) * ROWB
                           + (uint32_t)(ks * 16 + ((l >> 3) & 1) * 8) * 2);
            #pragma unroll
            for (int mt = 0; mt < 4; ++mt)
                #pragma unroll
                for (int nt = 0; nt < 4; ++nt)
                    mma16816(acc[mt][nt], afr[mt], bfr[nt]);
        }
        __syncthreads();
        if (c + 3 < NCHUNK) load_chunk(c + 3, s);
    }

    // ---- epilogue: per-row top-2 over this 128-codeword block ----
    #pragma unroll
    for (int mt = 0; mt < 4; ++mt) {
        #pragma unroll
        for (int rr = 0; rr < 2; ++rr) {
            const int rowCTA = wm * 64 + mt * 16 + (l >> 2) + rr * 8;
            float v1 = 3.4e38f, v2 = 3.4e38f;
            int   k1 = 0;
            #pragma unroll
            for (int nt = 0; nt < 4; ++nt) {
                #pragma unroll
                for (int cc = 0; cc < 2; ++cc) {
                    const int col = wn * 32 + nt * 8 + (l & 3) * 2 + cc;
                    const float v = sEsq[col] - acc[mt][nt][rr * 2 + cc];
                    if (v < v1)      { v2 = v1; v1 = v; k1 = k0 + col; }
                    else if (v < v2) { v2 = v; }
                }
            }
            #pragma unroll
            for (int off = 1; off <= 2; off <<= 1) {
                const float ov1 = __shfl_xor_sync(0xffffffffu, v1, off);
                const float ov2 = __shfl_xor_sync(0xffffffffu, v2, off);
                const int   ok1 = __shfl_xor_sync(0xffffffffu, k1, off);
                if (ov1 < v1 || (ov1 == v1 && ok1 < k1)) {
                    v2 = fminf(v1, ov2); v1 = ov1; k1 = ok1;
                } else {
                    v2 = fminf(v2, ov1);
                }
            }
            if ((l & 3) == 0) {
                sv1[wn][rowCTA] = v1; sv2[wn][rowCTA] = v2; sk1[wn][rowCTA] = k1;
            }
        }
    }
    __syncthreads();
    if (tid < 128) {
        float v1 = sv1[0][tid], v2 = sv2[0][tid];
        int   k1 = sk1[0][tid];
        #pragma unroll
        for (int w = 1; w < 4; ++w) {
            const float pv1 = sv1[w][tid], pv2 = sv2[w][tid];
            const int   pk  = sk1[w][tid];
            if (pv1 < v1 || (pv1 == v1 && pk < k1)) {
                v2 = fminf(v1, pv2); v1 = pv1; k1 = pk;
            } else {
                v2 = fminf(v2, pv1);
            }
        }
        g_p1[kb * NPOS + n0 + tid] = v1;
        g_p2[kb * NPOS + n0 + tid] = v2;
        g_pk[kb * NPOS + n0 + tid] = k1;
    }
}

// ---------------------------------------------------------------------------
// Kernel: combine 8 k-block partials -> argmin + repair flags
// ---------------------------------------------------------------------------
__global__ void k_final() {
    const int n = blockIdx.x * 256 + threadIdx.x;
    float v1 = 3.4e38f, v2 = 3.4e38f;
    int k1 = 0x7fffffff;
    #pragma unroll
    for (int kb = 0; kb < 8; ++kb) {
        const float pv1 = g_p1[kb * NPOS + n];
        const float pv2 = g_p2[kb * NPOS + n];
        const int   pk  = g_pk[kb * NPOS + n];
        if (pv1 < v1 || (pv1 == v1 && pk < k1)) {
            v2 = fminf(v1, pv2); v1 = pv1; k1 = pk;
        } else {
            v2 = fminf(v2, pv1);
        }
    }
    g_idx[n] = k1;
    if (v2 - v1 < 0.1f) {            // fp16 GEMM noise margin (~8 sigma)
        int slot = atomicAdd(&g_nrep, 1);
        g_rep[slot] = n;
    }
}

// ---------------------------------------------------------------------------
// Kernel: exact fp32 re-argmin for flagged near-tie positions
// ---------------------------------------------------------------------------
__global__ void k_repair(const float* __restrict__ inp, const float* __restrict__ emb) {
    __shared__ float xs[256];
    __shared__ float rv[256];
    __shared__ int   rk[256];
    const int t = threadIdx.x;
    const int nrep = g_nrep;
    for (int i = blockIdx.x; i < nrep; i += gridDim.x) {
        const int n = g_rep[i];
        const int b = n >> 10, hw = n & 1023;
        xs[t] = inp[(size_t)b * (CDIM * 1024) + (size_t)t * 1024 + hw];
        __syncthreads();
        float best = 3.4e38f; int bk = 0x7fffffff;
        #pragma unroll 1
        for (int kk = 0; kk < 4; ++kk) {
            const int k = t + kk * 256;
            float dot = 0.f;
            #pragma unroll 8
            for (int c = 0; c < CDIM; ++c) dot = fmaf(xs[c], emb[c * KEMB + k], dot);
            const float v = g_esqh[k] - dot;
            if (v < best || (v == best && k < bk)) { best = v; bk = k; }
        }
        rv[t] = best; rk[t] = bk;
        __syncthreads();
        for (int s = 128; s; s >>= 1) {
            if (t < s) {
                if (rv[t + s] < rv[t] || (rv[t + s] == rv[t] && rk[t + s] < rk[t])) {
                    rv[t] = rv[t + s]; rk[t] = rk[t + s];
                }
            }
            __syncthreads();
        }
        if (t == 0) g_idx[n] = rk[0];
        __syncthreads();
    }
}

// ---------------------------------------------------------------------------
// Kernel: quantize gather + loss partials
// ---------------------------------------------------------------------------
__global__ void k_quant(const float* __restrict__ inp, const float* __restrict__ emb,
                        float* __restrict__ outq) {
    const int t   = threadIdx.x;
    const int blk = blockIdx.x;
    const int b   = blk >> 3;
    const int hw  = (blk & 7) * 128 + t;
    const int n   = b * 1024 + hw;
    const int idx = g_idx[n];
    const size_t base = (size_t)b * (CDIM * 1024) + hw;

    float ls = 0.f;
    #pragma unroll 4
    for (int c = 0; c < CDIM; ++c) {
        float x = inp[base + (size_t)c * 1024];
        float e = emb[c * KEMB + idx];
        outq[base + (size_t)c * 1024] = e;
        float d = e - x;
        ls = fmaf(d, d, ls);
    }
    __shared__ float red[128];
    red[t] = ls;
    __syncthreads();
    #pragma unroll
    for (int s = 64; s; s >>= 1) {
        if (t < s) red[t] += red[t + s];
        __syncthreads();
    }
    if (t == 0) atomicAdd(&g_loss, red[0]);
}

// ---------------------------------------------------------------------------
// Kernel: onehot + loss scalar
// ---------------------------------------------------------------------------
__global__ void k_onehot(float* __restrict__ d_out) {
    float* oh = d_out + (QELEMS + 1);
    const int t  = threadIdx.x;
    const int r0 = blockIdx.x * 8;
    #pragma unroll
    for (int rr = 0; rr < 8; ++rr) {
        const int n   = r0 + rr;
        const int idx = g_idx[n];
        const size_t base = (size_t)n * KEMB;
        #pragma unroll
        for (int p = 0; p < 4; ++p) {
            const int j = t + p * 256;
            oh[base + j] = (j == idx) ? 1.0f : 0.0f;
        }
    }
    if (blockIdx.x == 0 && t == 0) {
        d_out[QELEMS] = 1.25f * g_loss / (float)QELEMS;
    }
}

// ---------------------------------------------------------------------------
extern "C" void kernel_launch(void* const* d_in, const int* in_sizes, int n_in,
                              void* d_out, int out_size) {
    const float* inp = (const float*)d_in[0];
    const float* emb = (const float*)d_in[1];
    float* out = (float*)d_out;

    cudaFuncSetAttribute(k_mma, cudaFuncAttributeMaxDynamicSharedMemorySize, MMA_SMEM);

    k_esq<<<4, 256>>>(emb);
    k_split<<<32, 256>>>(emb, 1);
    k_split<<<1024, 256>>>(inp, 0);
    k_mma<<<2048, 256, MMA_SMEM>>>();
    k_final<<<128, 256>>>();
    k_repair<<<256, 256>>>(inp, emb);
    k_quant<<<256, 128>>>(inp, emb, out);
    k_onehot<<<4096, 256>>>(out);
}

// round 6
// speedup vs baseline: 1.5444x; 1.5444x over previous
#include <cuda_runtime.h>
#include <cuda_fp16.h>
#include <cstdint>

// VQ argmin: 32768 positions x 1024 codewords, C=256.
// inputs [32,256,32,32] f32, embed [256,1024] f32.
// out = concat(quantize_st [8388608], loss [1], onehot [33554432]) f32.
// fp16 HMMA GEMM for scores + exact fp32 batched repair for near-ties.

#define NPOS   32768
#define KEMB   1024
#define CDIM   256
#define QELEMS 8388608

// ---------------------------------------------------------------------------
// device scratch
// ---------------------------------------------------------------------------
__device__ __align__(256) __half g_Xh[NPOS * CDIM];
__device__ __align__(256) __half g_Eh[KEMB * CDIM];
__device__ __align__(256) float  g_Et[KEMB * CDIM];   // fp32 transposed codebook [k][c]
__device__ float g_esqh[KEMB];
__device__ int   g_idx[NPOS];
__device__ float g_loss;
__device__ int   g_nrep;
__device__ int   g_rep[NPOS];
__device__ float g_p1[8 * NPOS];
__device__ float g_p2[8 * NPOS];
__device__ int   g_pk[8 * NPOS];

// ---------------------------------------------------------------------------
// helpers
// ---------------------------------------------------------------------------
__device__ __forceinline__ uint32_t s2u(const void* p) {
    uint32_t a;
    asm("{ .reg .u64 t; cvta.to.shared.u64 t, %1; cvt.u32.u64 %0, t; }" : "=r"(a) : "l"(p));
    return a;
}
__device__ __forceinline__ void cp16(uint32_t s, const void* g) {
    asm volatile("cp.async.cg.shared.global [%0], [%1], 16;" :: "r"(s), "l"(g));
}
__device__ __forceinline__ void cpcommit() { asm volatile("cp.async.commit_group;"); }
template <int N>
__device__ __forceinline__ void cpwait() { asm volatile("cp.async.wait_group %0;" :: "n"(N)); }

__device__ __forceinline__ void ldm_x4(uint32_t& r0, uint32_t& r1, uint32_t& r2, uint32_t& r3,
                                       uint32_t addr) {
    asm volatile("ldmatrix.sync.aligned.m8n8.x4.shared.b16 {%0,%1,%2,%3}, [%4];"
                 : "=r"(r0), "=r"(r1), "=r"(r2), "=r"(r3) : "r"(addr));
}
__device__ __forceinline__ void ldm_x2(uint32_t& r0, uint32_t& r1, uint32_t addr) {
    asm volatile("ldmatrix.sync.aligned.m8n8.x2.shared.b16 {%0,%1}, [%2];"
                 : "=r"(r0), "=r"(r1) : "r"(addr));
}
__device__ __forceinline__ void mma16816(float* d, const uint32_t* a, const uint32_t* b) {
    asm volatile(
        "mma.sync.aligned.m16n8k16.row.col.f32.f16.f16.f32 "
        "{%0,%1,%2,%3}, {%4,%5,%6,%7}, {%8,%9}, {%0,%1,%2,%3};"
        : "+f"(d[0]), "+f"(d[1]), "+f"(d[2]), "+f"(d[3])
        : "r"(a[0]), "r"(a[1]), "r"(a[2]), "r"(a[3]), "r"(b[0]), "r"(b[1]));
}

// ---------------------------------------------------------------------------
// Kernel: 0.5*||e_k||^2 + counter reset
// ---------------------------------------------------------------------------
__global__ void k_esq(const float* __restrict__ emb) {
    int k = blockIdx.x * 256 + threadIdx.x;
    float s = 0.f;
    #pragma unroll 8
    for (int c = 0; c < CDIM; ++c) {
        float e = emb[c * KEMB + k];
        s = fmaf(e, e, s);
    }
    g_esqh[k] = 0.5f * s;
    if (k == 0) { g_loss = 0.f; g_nrep = 0; }
}

// ---------------------------------------------------------------------------
// Kernel: transpose + fp16 convert; embed pass also emits fp32 g_Et[k][c]
// ---------------------------------------------------------------------------
__global__ void k_split(const float* __restrict__ src, int is_embed) {
    __half* __restrict__ dst = is_embed ? g_Eh : g_Xh;
    __shared__ float Xs[32][257];
    const int t = threadIdx.x;
    const int s = blockIdx.x >> 5;
    const int hw0 = (blockIdx.x & 31) * 32;
    const int lane = t & 31, w = t >> 5;
    const float* sp = src + (size_t)s * (CDIM * 1024);

    #pragma unroll
    for (int i = 0; i < 32; ++i) {
        int c = w + i * 8;
        Xs[lane][c] = sp[(size_t)c * 1024 + hw0 + lane];
    }
    __syncthreads();

    #pragma unroll
    for (int rr = 0; rr < 4; ++rr) {
        int r = w * 4 + rr;
        size_t ob = ((size_t)s * 1024 + hw0 + r) * CDIM;
        #pragma unroll
        for (int j = 0; j < 8; ++j) {
            int c = lane + 32 * j;
            float x = Xs[r][c];
            dst[ob + c] = __float2half_rn(x);
            if (is_embed) g_Et[ob + c] = x;
        }
    }
}

// ---------------------------------------------------------------------------
// Kernel: fp16 HMMA GEMM tile + per-row top-2.
// Grid 2048: nb = bid>>3 (128 positions), kb = bid&7 (128 codewords).
// ---------------------------------------------------------------------------
#define ROWB   80
#define STG_A  (128 * ROWB)
#define STG    (2 * STG_A)
#define NCHUNK 8
#define MMA_SMEM (3 * STG)

__global__ __launch_bounds__(256, 2) void k_mma() {
    extern __shared__ char dsm[];
    const uint32_t sb = s2u(dsm);
    __shared__ float sEsq[128];
    __shared__ float sv1[4][128];
    __shared__ float sv2[4][128];
    __shared__ int   sk1[4][128];

    const int tid = threadIdx.x;
    const int l   = tid & 31;
    const int wid = tid >> 5;
    const int wm  = wid & 1;
    const int wn  = wid >> 1;

    const int nb = blockIdx.x >> 3;
    const int kb = blockIdx.x & 7;
    const int n0 = nb * 128;
    const int k0 = kb * 128;

    if (tid < 128) sEsq[tid] = g_esqh[k0 + tid];

    const __half* Ag0 = g_Xh + (size_t)n0 * CDIM;
    const __half* Bg0 = g_Eh + (size_t)k0 * CDIM;

    auto load_chunk = [&](int c, int s) {
        const __half* Ag = Ag0 + c * 32;
        const __half* Bg = Bg0 + c * 32;
        const uint32_t ab = sb + s * STG, bbs = ab + STG_A;
        #pragma unroll
        for (int u = 0; u < 2; ++u) {
            const int idx = tid + u * 256;
            const int row = idx >> 2, q = idx & 3;
            cp16(ab  + row * ROWB + q * 16, Ag + (size_t)row * CDIM + q * 8);
            cp16(bbs + row * ROWB + q * 16, Bg + (size_t)row * CDIM + q * 8);
        }
        cpcommit();
    };

    float acc[4][4][4];
    #pragma unroll
    for (int i = 0; i < 4; ++i)
        #pragma unroll
        for (int j = 0; j < 4; ++j)
            #pragma unroll
            for (int r = 0; r < 4; ++r) acc[i][j][r] = 0.f;

    load_chunk(0, 0);
    load_chunk(1, 1);
    load_chunk(2, 2);

    #pragma unroll 1
    for (int c = 0; c < NCHUNK; ++c) {
        if (c <= NCHUNK - 3)      cpwait<2>();
        else if (c == NCHUNK - 2) cpwait<1>();
        else                      cpwait<0>();
        __syncthreads();

        const int s = c % 3;
        const uint32_t ab = sb + s * STG, bbs = ab + STG_A;
        #pragma unroll
        for (int ks = 0; ks < 2; ++ks) {
            uint32_t afr[4][4], bfr[4][2];
            #pragma unroll
            for (int mt = 0; mt < 4; ++mt)
                ldm_x4(afr[mt][0], afr[mt][1], afr[mt][2], afr[mt][3],
                       ab + (uint32_t)(wm * 64 + mt * 16 + (l & 15)) * ROWB
                          + (uint32_t)(ks * 16 + (l >> 4) * 8) * 2);
            #pragma unroll
            for (int nt = 0; nt < 4; ++nt)
                ldm_x2(bfr[nt][0], bfr[nt][1],
                       bbs + (uint32_t)(wn * 32 + nt * 8 + (l & 7)) * ROWB
                           + (uint32_t)(ks * 16 + ((l >> 3) & 1) * 8) * 2);
            #pragma unroll
            for (int mt = 0; mt < 4; ++mt)
                #pragma unroll
                for (int nt = 0; nt < 4; ++nt)
                    mma16816(acc[mt][nt], afr[mt], bfr[nt]);
        }
        __syncthreads();
        if (c + 3 < NCHUNK) load_chunk(c + 3, s);
    }

    #pragma unroll
    for (int mt = 0; mt < 4; ++mt) {
        #pragma unroll
        for (int rr = 0; rr < 2; ++rr) {
            const int rowCTA = wm * 64 + mt * 16 + (l >> 2) + rr * 8;
            float v1 = 3.4e38f, v2 = 3.4e38f;
            int   k1 = 0;
            #pragma unroll
            for (int nt = 0; nt < 4; ++nt) {
                #pragma unroll
                for (int cc = 0; cc < 2; ++cc) {
                    const int col = wn * 32 + nt * 8 + (l & 3) * 2 + cc;
                    const float v = sEsq[col] - acc[mt][nt][rr * 2 + cc];
                    if (v < v1)      { v2 = v1; v1 = v; k1 = k0 + col; }
                    else if (v < v2) { v2 = v; }
                }
            }
            #pragma unroll
            for (int off = 1; off <= 2; off <<= 1) {
                const float ov1 = __shfl_xor_sync(0xffffffffu, v1, off);
                const float ov2 = __shfl_xor_sync(0xffffffffu, v2, off);
                const int   ok1 = __shfl_xor_sync(0xffffffffu, k1, off);
                if (ov1 < v1 || (ov1 == v1 && ok1 < k1)) {
                    v2 = fminf(v1, ov2); v1 = ov1; k1 = ok1;
                } else {
                    v2 = fminf(v2, ov1);
                }
            }
            if ((l & 3) == 0) {
                sv1[wn][rowCTA] = v1; sv2[wn][rowCTA] = v2; sk1[wn][rowCTA] = k1;
            }
        }
    }
    __syncthreads();
    if (tid < 128) {
        float v1 = sv1[0][tid], v2 = sv2[0][tid];
        int   k1 = sk1[0][tid];
        #pragma unroll
        for (int w = 1; w < 4; ++w) {
            const float pv1 = sv1[w][tid], pv2 = sv2[w][tid];
            const int   pk  = sk1[w][tid];
            if (pv1 < v1 || (pv1 == v1 && pk < k1)) {
                v2 = fminf(v1, pv2); v1 = pv1; k1 = pk;
            } else {
                v2 = fminf(v2, pv1);
            }
        }
        g_p1[kb * NPOS + n0 + tid] = v1;
        g_p2[kb * NPOS + n0 + tid] = v2;
        g_pk[kb * NPOS + n0 + tid] = k1;
    }
}

// ---------------------------------------------------------------------------
// Kernel: combine 8 k-block partials -> argmin + repair flags
// ---------------------------------------------------------------------------
__global__ void k_final() {
    const int n = blockIdx.x * 256 + threadIdx.x;
    float v1 = 3.4e38f, v2 = 3.4e38f;
    int k1 = 0x7fffffff;
    #pragma unroll
    for (int kb = 0; kb < 8; ++kb) {
        const float pv1 = g_p1[kb * NPOS + n];
        const float pv2 = g_p2[kb * NPOS + n];
        const int   pk  = g_pk[kb * NPOS + n];
        if (pv1 < v1 || (pv1 == v1 && pk < k1)) {
            v2 = fminf(v1, pv2); v1 = pv1; k1 = pk;
        } else {
            v2 = fminf(v2, pv1);
        }
    }
    g_idx[n] = k1;
    if (v2 - v1 < 0.1f) {
        int slot = atomicAdd(&g_nrep, 1);
        g_rep[slot] = n;
    }
}

// ---------------------------------------------------------------------------
// Kernel: batched exact fp32 re-argmin. 8 positions per block batch;
// codebook streamed through smem in 32-row chunks (amortized 8x).
// Thread (p = tid>>5, kk = tid&31); one warp per position.
// ---------------------------------------------------------------------------
__global__ __launch_bounds__(256) void k_repair(const float* __restrict__ inp) {
    __shared__ float xs[8][257];
    __shared__ float Ec[32][257];
    const int t = threadIdx.x;
    const int p = t >> 5, kk = t & 31;
    const int nrep = g_nrep;

    for (int base = blockIdx.x * 8; base < nrep; base += gridDim.x * 8) {
        const int cnt = min(8, nrep - base);
        for (int i = t; i < cnt * 256; i += 256) {
            const int pp = i >> 8, c = i & 255;
            const int n = g_rep[base + pp];
            const int b = n >> 10, hw = n & 1023;
            xs[pp][c] = inp[(size_t)b * (CDIM * 1024) + (size_t)c * 1024 + hw];
        }
        __syncthreads();

        float best = 3.4e38f;
        int   bk = 0x7fffffff;
        #pragma unroll 1
        for (int k0 = 0; k0 < KEMB; k0 += 32) {
            for (int i = t; i < 32 * 256; i += 256) {
                const int rr = i >> 8, c = i & 255;
                Ec[rr][c] = g_Et[(k0 + rr) * CDIM + c];
            }
            __syncthreads();
            if (p < cnt) {
                float dot = 0.f;
                #pragma unroll 8
                for (int c = 0; c < CDIM; ++c) dot = fmaf(xs[p][c], Ec[kk][c], dot);
                const float v = g_esqh[k0 + kk] - dot;
                const int k = k0 + kk;
                if (v < best || (v == best && k < bk)) { best = v; bk = k; }
            }
            __syncthreads();
        }
        #pragma unroll
        for (int off = 16; off; off >>= 1) {
            const float ov = __shfl_xor_sync(0xffffffffu, best, off);
            const int   ok = __shfl_xor_sync(0xffffffffu, bk, off);
            if (ov < best || (ov == best && ok < bk)) { best = ov; bk = ok; }
        }
        if (p < cnt && kk == 0) g_idx[g_rep[base + p]] = bk;
        __syncthreads();
    }
}

// ---------------------------------------------------------------------------
// Kernel: quantize gather + loss. 32 positions per block; selected codebook
// rows staged in smem via coalesced row reads; coalesced strided-c writes.
// ---------------------------------------------------------------------------
__global__ __launch_bounds__(256) void k_quant(const float* __restrict__ inp,
                                               float* __restrict__ outq) {
    __shared__ float eq[32][257];
    __shared__ int   sidx[32];
    const int t  = threadIdx.x;
    const int n0 = blockIdx.x * 32;
    const int b  = n0 >> 10;
    const int hw0 = n0 & 1023;

    if (t < 32) sidx[t] = g_idx[n0 + t];
    __syncthreads();
    #pragma unroll 1
    for (int j = 0; j < 32; ++j) {
        eq[j][t] = g_Et[(size_t)sidx[j] * CDIM + t];
    }
    __syncthreads();

    const int hw_l = t & 31;
    const int cg   = t >> 5;
    const size_t base = (size_t)b * (CDIM * 1024) + hw0 + hw_l;

    float ls = 0.f;
    #pragma unroll 4
    for (int cb = 0; cb < 32; ++cb) {
        const int c = cb * 8 + cg;
        const size_t a = base + (size_t)c * 1024;
        const float x = inp[a];
        const float e = eq[hw_l][c];
        outq[a] = e;
        const float d = e - x;
        ls = fmaf(d, d, ls);
    }

    __shared__ float red[256];
    red[t] = ls;
    __syncthreads();
    #pragma unroll
    for (int s = 128; s; s >>= 1) {
        if (t < s) red[t] += red[t + s];
        __syncthreads();
    }
    if (t == 0) atomicAdd(&g_loss, red[0]);
}

// ---------------------------------------------------------------------------
// Kernel: onehot + loss scalar
// ---------------------------------------------------------------------------
__global__ void k_onehot(float* __restrict__ d_out) {
    float* oh = d_out + (QELEMS + 1);
    const int t  = threadIdx.x;
    const int r0 = blockIdx.x * 8;
    #pragma unroll
    for (int rr = 0; rr < 8; ++rr) {
        const int n   = r0 + rr;
        const int idx = g_idx[n];
        const size_t base = (size_t)n * KEMB;
        #pragma unroll
        for (int p = 0; p < 4; ++p) {
            const int j = t + p * 256;
            oh[base + j] = (j == idx) ? 1.0f : 0.0f;
        }
    }
    if (blockIdx.x == 0 && t == 0) {
        d_out[QELEMS] = 1.25f * g_loss / (float)QELEMS;
    }
}

// ---------------------------------------------------------------------------
extern "C" void kernel_launch(void* const* d_in, const int* in_sizes, int n_in,
                              void* d_out, int out_size) {
    const float* inp = (const float*)d_in[0];
    const float* emb = (const float*)d_in[1];
    float* out = (float*)d_out;

    cudaFuncSetAttribute(k_mma, cudaFuncAttributeMaxDynamicSharedMemorySize, MMA_SMEM);

    k_esq<<<4, 256>>>(emb);
    k_split<<<32, 256>>>(emb, 1);
    k_split<<<1024, 256>>>(inp, 0);
    k_mma<<<2048, 256, MMA_SMEM>>>();
    k_final<<<128, 256>>>();
    k_repair<<<148, 256>>>(inp);
    k_quant<<<1024, 256>>>(inp, out);
    k_onehot<<<4096, 256>>>(out);
}

// round 7
// speedup vs baseline: 1.5923x; 1.0310x over previous
#include <cuda_runtime.h>
#include <cuda_fp16.h>
#include <cstdint>

// VQ argmin: 32768 positions x 1024 codewords, C=256.
// inputs [32,256,32,32] f32, embed [256,1024] f32.
// out = concat(quantize_st [8388608], loss [1], onehot [33554432]) f32.
// fp16 HMMA GEMM for scores + exact fp32 batched repair for near-ties.

#define NPOS   32768
#define KEMB   1024
#define CDIM   256
#define QELEMS 8388608

// ---------------------------------------------------------------------------
// device scratch
// ---------------------------------------------------------------------------
__device__ __align__(256) __half g_Xh[NPOS * CDIM];
__device__ __align__(256) __half g_Eh[KEMB * CDIM];
__device__ __align__(256) float  g_Et[KEMB * CDIM];   // fp32 codebook [k][c]
__device__ float g_esqh[KEMB];
__device__ int   g_idx[NPOS];
__device__ float g_loss;
__device__ int   g_nrep;
__device__ int   g_rep[NPOS];

// ---------------------------------------------------------------------------
// helpers
// ---------------------------------------------------------------------------
__device__ __forceinline__ uint32_t s2u(const void* p) {
    uint32_t a;
    asm("{ .reg .u64 t; cvta.to.shared.u64 t, %1; cvt.u32.u64 %0, t; }" : "=r"(a) : "l"(p));
    return a;
}
__device__ __forceinline__ void cp16(uint32_t s, const void* g) {
    asm volatile("cp.async.cg.shared.global [%0], [%1], 16;" :: "r"(s), "l"(g));
}
__device__ __forceinline__ void cpcommit() { asm volatile("cp.async.commit_group;"); }
template <int N>
__device__ __forceinline__ void cpwait() { asm volatile("cp.async.wait_group %0;" :: "n"(N)); }

__device__ __forceinline__ void ldm_x4(uint32_t& r0, uint32_t& r1, uint32_t& r2, uint32_t& r3,
                                       uint32_t addr) {
    asm volatile("ldmatrix.sync.aligned.m8n8.x4.shared.b16 {%0,%1,%2,%3}, [%4];"
                 : "=r"(r0), "=r"(r1), "=r"(r2), "=r"(r3) : "r"(addr));
}
__device__ __forceinline__ void mma16816(float* d, const uint32_t* a, const uint32_t* b) {
    asm volatile(
        "mma.sync.aligned.m16n8k16.row.col.f32.f16.f16.f32 "
        "{%0,%1,%2,%3}, {%4,%5,%6,%7}, {%8,%9}, {%0,%1,%2,%3};"
        : "+f"(d[0]), "+f"(d[1]), "+f"(d[2]), "+f"(d[3])
        : "r"(a[0]), "r"(a[1]), "r"(a[2]), "r"(a[3]), "r"(b[0]), "r"(b[1]));
}

// ---------------------------------------------------------------------------
// Kernel: embed prep — transpose to [k][c], fp16 + fp32 copies, 0.5||e||^2,
// and global counter resets. Grid 32 x 256.
// ---------------------------------------------------------------------------
__global__ void k_prep_embed(const float* __restrict__ src) {
    __shared__ float Xs[32][257];
    const int t = threadIdx.x;
    const int hw0 = blockIdx.x * 32;          // k range
    const int lane = t & 31, w = t >> 5;

    #pragma unroll
    for (int i = 0; i < 32; ++i) {
        int c = w + i * 8;
        Xs[lane][c] = src[(size_t)c * 1024 + hw0 + lane];
    }
    __syncthreads();

    #pragma unroll
    for (int rr = 0; rr < 4; ++rr) {
        int r = w * 4 + rr;
        size_t ob = (size_t)(hw0 + r) * CDIM;
        #pragma unroll
        for (int j = 0; j < 8; ++j) {
            int c = lane + 32 * j;
            float x = Xs[r][c];
            g_Eh[ob + c] = __float2half_rn(x);
            g_Et[ob + c] = x;
        }
    }
    if (t < 32) {
        float s2 = 0.f;
        #pragma unroll 8
        for (int c = 0; c < CDIM; ++c) s2 = fmaf(Xs[t][c], Xs[t][c], s2);
        g_esqh[hw0 + t] = 0.5f * s2;
    }
    if (blockIdx.x == 0 && t == 0) { g_loss = 0.f; g_nrep = 0; }
}

// ---------------------------------------------------------------------------
// Kernel: input prep — transpose + fp16 convert. Grid 1024 x 256.
// ---------------------------------------------------------------------------
__global__ void k_prep_x(const float* __restrict__ src) {
    __shared__ float Xs[32][257];
    const int t = threadIdx.x;
    const int s = blockIdx.x >> 5;
    const int hw0 = (blockIdx.x & 31) * 32;
    const int lane = t & 31, w = t >> 5;
    const float* sp = src + (size_t)s * (CDIM * 1024);

    #pragma unroll
    for (int i = 0; i < 32; ++i) {
        int c = w + i * 8;
        Xs[lane][c] = sp[(size_t)c * 1024 + hw0 + lane];
    }
    __syncthreads();

    #pragma unroll
    for (int rr = 0; rr < 4; ++rr) {
        int r = w * 4 + rr;
        size_t ob = ((size_t)s * 1024 + hw0 + r) * CDIM;
        #pragma unroll
        for (int j = 0; j < 8; ++j) {
            int c = lane + 32 * j;
            Xs2half: ;
            g_Xh[ob + c] = __float2half_rn(Xs[r][c]);
        }
    }
}

// ---------------------------------------------------------------------------
// Kernel: fp16 HMMA GEMM + full argmin. Grid 256: one CTA per 128 positions,
// loops all 8 codeword blocks (64 chunks of BK=32, 3-stage cp.async pipeline).
// Writes g_idx + repair flags directly (no partial arrays, no combine kernel).
// ---------------------------------------------------------------------------
#define ROWB   80
#define STG_A  (128 * ROWB)
#define STG    (2 * STG_A)
#define NCHUNK 64
#define MMA_SMEM (3 * STG)

__global__ __launch_bounds__(256, 2) void k_mma() {
    extern __shared__ char dsm[];
    const uint32_t sb = s2u(dsm);
    __shared__ float sEsq[1024];
    __shared__ float sv1[4][128];
    __shared__ float sv2[4][128];
    __shared__ int   sk1[4][128];

    const int tid = threadIdx.x;
    const int l   = tid & 31;
    const int wid = tid >> 5;
    const int wm  = wid & 1;
    const int wn  = wid >> 1;

    const int n0 = blockIdx.x * 128;

    for (int i = tid; i < 1024; i += 256) sEsq[i] = g_esqh[i];

    const __half* Ag0 = g_Xh + (size_t)n0 * CDIM;

    auto load_chunk = [&](int ci) {
        const int kb = ci >> 3, c = ci & 7;
        const __half* Ag = Ag0 + c * 32;
        const __half* Bg = g_Eh + (size_t)(kb * 128) * CDIM + c * 32;
        const uint32_t ab = sb + (ci % 3) * STG, bbs = ab + STG_A;
        #pragma unroll
        for (int u = 0; u < 2; ++u) {
            const int idx = tid + u * 256;
            const int row = idx >> 2, q = idx & 3;
            cp16(ab  + row * ROWB + q * 16, Ag + (size_t)row * CDIM + q * 8);
            cp16(bbs + row * ROWB + q * 16, Bg + (size_t)row * CDIM + q * 8);
        }
        cpcommit();
    };

    // running top-2 for row = tid (threads 0..127)
    float rv1 = 3.4e38f, rv2 = 3.4e38f;
    int   rk1 = 0;

    load_chunk(0);
    load_chunk(1);
    load_chunk(2);

    #pragma unroll 1
    for (int kb = 0; kb < 8; ++kb) {
        const int k0 = kb * 128;
        float acc[4][4][4];
        #pragma unroll
        for (int i = 0; i < 4; ++i)
            #pragma unroll
            for (int j = 0; j < 4; ++j)
                #pragma unroll
                for (int r = 0; r < 4; ++r) acc[i][j][r] = 0.f;

        #pragma unroll 1
        for (int c = 0; c < 8; ++c) {
            const int ci = kb * 8 + c;
            if (ci <= NCHUNK - 3)      cpwait<2>();
            else if (ci == NCHUNK - 2) cpwait<1>();
            else                       cpwait<0>();
            __syncthreads();

            const uint32_t ab = sb + (ci % 3) * STG, bbs = ab + STG_A;
            #pragma unroll
            for (int ks = 0; ks < 2; ++ks) {
                uint32_t afr[4][4], bfr[4][2];
                #pragma unroll
                for (int mt = 0; mt < 4; ++mt)
                    ldm_x4(afr[mt][0], afr[mt][1], afr[mt][2], afr[mt][3],
                           ab + (uint32_t)(wm * 64 + mt * 16 + (l & 15)) * ROWB
                              + (uint32_t)(ks * 16 + (l >> 4) * 8) * 2);
                #pragma unroll
                for (int ntp = 0; ntp < 2; ++ntp)
                    ldm_x4(bfr[2 * ntp][0], bfr[2 * ntp][1],
                           bfr[2 * ntp + 1][0], bfr[2 * ntp + 1][1],
                           bbs + (uint32_t)(wn * 32 + ntp * 16 + ((l >> 4) & 1) * 8 + (l & 7)) * ROWB
                               + (uint32_t)(ks * 16 + ((l >> 3) & 1) * 8) * 2);
                #pragma unroll
                for (int mt = 0; mt < 4; ++mt)
                    #pragma unroll
                    for (int nt = 0; nt < 4; ++nt)
                        mma16816(acc[mt][nt], afr[mt], bfr[nt]);
            }
            __syncthreads();
            if (ci + 3 < NCHUNK) load_chunk(ci + 3);
        }

        // ---- epilogue for this codeword block ----
        #pragma unroll
        for (int mt = 0; mt < 4; ++mt) {
            #pragma unroll
            for (int rr = 0; rr < 2; ++rr) {
                const int rowCTA = wm * 64 + mt * 16 + (l >> 2) + rr * 8;
                float v1 = 3.4e38f, v2 = 3.4e38f;
                int   k1 = 0;
                #pragma unroll
                for (int nt = 0; nt < 4; ++nt) {
                    #pragma unroll
                    for (int cc = 0; cc < 2; ++cc) {
                        const int col = wn * 32 + nt * 8 + (l & 3) * 2 + cc;
                        const float v = sEsq[k0 + col] - acc[mt][nt][rr * 2 + cc];
                        if (v < v1)      { v2 = v1; v1 = v; k1 = k0 + col; }
                        else if (v < v2) { v2 = v; }
                    }
                }
                #pragma unroll
                for (int off = 1; off <= 2; off <<= 1) {
                    const float ov1 = __shfl_xor_sync(0xffffffffu, v1, off);
                    const float ov2 = __shfl_xor_sync(0xffffffffu, v2, off);
                    const int   ok1 = __shfl_xor_sync(0xffffffffu, k1, off);
                    if (ov1 < v1 || (ov1 == v1 && ok1 < k1)) {
                        v2 = fminf(v1, ov2); v1 = ov1; k1 = ok1;
                    } else {
                        v2 = fminf(v2, ov1);
                    }
                }
                if ((l & 3) == 0) {
                    sv1[wn][rowCTA] = v1; sv2[wn][rowCTA] = v2; sk1[wn][rowCTA] = k1;
                }
            }
        }
        __syncthreads();
        if (tid < 128) {
            #pragma unroll
            for (int w = 0; w < 4; ++w) {
                const float pv1 = sv1[w][tid], pv2 = sv2[w][tid];
                const int   pk  = sk1[w][tid];
                if (pv1 < rv1 || (pv1 == rv1 && pk < rk1)) {
                    rv2 = fminf(rv1, pv2); rv1 = pv1; rk1 = pk;
                } else {
                    rv2 = fminf(rv2, pv1);
                }
            }
        }
        __syncthreads();
    }

    if (tid < 128) {
        const int n = n0 + tid;
        g_idx[n] = rk1;
        if (rv2 - rv1 < 0.1f) {           // fp16 GEMM noise margin
            int slot = atomicAdd(&g_nrep, 1);
            g_rep[slot] = n;
        }
    }
}

// ---------------------------------------------------------------------------
// Kernel: batched exact fp32 re-argmin (8 positions/block batch, codebook
// streamed through smem in 32-row chunks).
// ---------------------------------------------------------------------------
__global__ __launch_bounds__(256) void k_repair(const float* __restrict__ inp) {
    __shared__ float xs[8][257];
    __shared__ float Ec[32][257];
    const int t = threadIdx.x;
    const int p = t >> 5, kk = t & 31;
    const int nrep = g_nrep;

    for (int base = blockIdx.x * 8; base < nrep; base += gridDim.x * 8) {
        const int cnt = min(8, nrep - base);
        for (int i = t; i < cnt * 256; i += 256) {
            const int pp = i >> 8, c = i & 255;
            const int n = g_rep[base + pp];
            const int b = n >> 10, hw = n & 1023;
            xs[pp][c] = inp[(size_t)b * (CDIM * 1024) + (size_t)c * 1024 + hw];
        }
        __syncthreads();

        float best = 3.4e38f;
        int   bk = 0x7fffffff;
        #pragma unroll 1
        for (int k0 = 0; k0 < KEMB; k0 += 32) {
            for (int i = t; i < 32 * 256; i += 256) {
                const int rr = i >> 8, c = i & 255;
                Ec[rr][c] = g_Et[(k0 + rr) * CDIM + c];
            }
            __syncthreads();
            if (p < cnt) {
                float dot = 0.f;
                #pragma unroll 8
                for (int c = 0; c < CDIM; ++c) dot = fmaf(xs[p][c], Ec[kk][c], dot);
                const float v = g_esqh[k0 + kk] - dot;
                const int k = k0 + kk;
                if (v < best || (v == best && k < bk)) { best = v; bk = k; }
            }
            __syncthreads();
        }
        #pragma unroll
        for (int off = 16; off; off >>= 1) {
            const float ov = __shfl_xor_sync(0xffffffffu, best, off);
            const int   ok = __shfl_xor_sync(0xffffffffu, bk, off);
            if (ov < best || (ov == best && ok < bk)) { best = ov; bk = ok; }
        }
        if (p < cnt && kk == 0) g_idx[g_rep[base + p]] = bk;
        __syncthreads();
    }
}

// ---------------------------------------------------------------------------
// Kernel: quantize gather + loss (32 positions/block, smem-staged rows)
// ---------------------------------------------------------------------------
__global__ __launch_bounds__(256) void k_quant(const float* __restrict__ inp,
                                               float* __restrict__ outq) {
    __shared__ float eq[32][257];
    __shared__ int   sidx[32];
    const int t  = threadIdx.x;
    const int n0 = blockIdx.x * 32;
    const int b  = n0 >> 10;
    const int hw0 = n0 & 1023;

    if (t < 32) sidx[t] = g_idx[n0 + t];
    __syncthreads();
    #pragma unroll 1
    for (int j = 0; j < 32; ++j) {
        eq[j][t] = g_Et[(size_t)sidx[j] * CDIM + t];
    }
    __syncthreads();

    const int hw_l = t & 31;
    const int cg   = t >> 5;
    const size_t base = (size_t)b * (CDIM * 1024) + hw0 + hw_l;

    float ls = 0.f;
    #pragma unroll 4
    for (int cb = 0; cb < 32; ++cb) {
        const int c = cb * 8 + cg;
        const size_t a = base + (size_t)c * 1024;
        const float x = inp[a];
        const float e = eq[hw_l][c];
        outq[a] = e;
        const float d = e - x;
        ls = fmaf(d, d, ls);
    }

    __shared__ float red[256];
    red[t] = ls;
    __syncthreads();
    #pragma unroll
    for (int s = 128; s; s >>= 1) {
        if (t < s) red[t] += red[t + s];
        __syncthreads();
    }
    if (t == 0) atomicAdd(&g_loss, red[0]);
}

// ---------------------------------------------------------------------------
// Kernel: onehot + loss scalar
// ---------------------------------------------------------------------------
__global__ void k_onehot(float* __restrict__ d_out) {
    float* oh = d_out + (QELEMS + 1);
    const int t  = threadIdx.x;
    const int r0 = blockIdx.x * 8;
    #pragma unroll
    for (int rr = 0; rr < 8; ++rr) {
        const int n   = r0 + rr;
        const int idx = g_idx[n];
        const size_t base = (size_t)n * KEMB;
        #pragma unroll
        for (int p = 0; p < 4; ++p) {
            const int j = t + p * 256;
            oh[base + j] = (j == idx) ? 1.0f : 0.0f;
        }
    }
    if (blockIdx.x == 0 && t == 0) {
        d_out[QELEMS] = 1.25f * g_loss / (float)QELEMS;
    }
}

// ---------------------------------------------------------------------------
extern "C" void kernel_launch(void* const* d_in, const int* in_sizes, int n_in,
                              void* d_out, int out_size) {
    const float* inp = (const float*)d_in[0];
    const float* emb = (const float*)d_in[1];
    float* out = (float*)d_out;

    cudaFuncSetAttribute(k_mma, cudaFuncAttributeMaxDynamicSharedMemorySize, MMA_SMEM);

    k_prep_embed<<<32, 256>>>(emb);
    k_prep_x<<<1024, 256>>>(inp);
    k_mma<<<256, 256, MMA_SMEM>>>();
    k_repair<<<296, 256>>>(inp);
    k_quant<<<1024, 256>>>(inp, out);
    k_onehot<<<4096, 256>>>(out);
}

// round 10
// speedup vs baseline: 2.3160x; 1.4545x over previous
#include <cuda_runtime.h>
#include <cuda_fp16.h>
#include <cstdint>

// VQ argmin: 32768 positions x 1024 codewords, C=256.
// inputs [32,256,32,32] f32, embed [256,1024] f32.
// out = concat(quantize_st [8388608], loss [1], onehot [33554432]) f32.
// fp16 HMMA GEMM for scores + exact fp32 repair (flat work grid + atomicMin).

#define NPOS   32768
#define KEMB   1024
#define CDIM   256
#define QELEMS 8388608

// ---------------------------------------------------------------------------
// device scratch
// ---------------------------------------------------------------------------
__device__ __align__(256) __half g_Xh[NPOS * CDIM];
__device__ __align__(256) __half g_Eh[KEMB * CDIM];
__device__ __align__(256) float  g_Et[KEMB * CDIM];   // fp32 codebook [k][c]
__device__ float g_esqh[KEMB];
__device__ int   g_idx[NPOS];
__device__ float g_loss;
__device__ int   g_nrep;
__device__ int   g_rep[NPOS];
__device__ unsigned long long g_best[NPOS];

// ---------------------------------------------------------------------------
// helpers
// ---------------------------------------------------------------------------
__device__ __forceinline__ uint32_t s2u(const void* p) {
    uint32_t a;
    asm("{ .reg .u64 t; cvta.to.shared.u64 t, %1; cvt.u32.u64 %0, t; }" : "=r"(a) : "l"(p));
    return a;
}
__device__ __forceinline__ void cp16(uint32_t s, const void* g) {
    asm volatile("cp.async.cg.shared.global [%0], [%1], 16;" :: "r"(s), "l"(g));
}
__device__ __forceinline__ void cpcommit() { asm volatile("cp.async.commit_group;"); }
template <int N>
__device__ __forceinline__ void cpwait() { asm volatile("cp.async.wait_group %0;" :: "n"(N)); }

__device__ __forceinline__ void ldm_x4(uint32_t& r0, uint32_t& r1, uint32_t& r2, uint32_t& r3,
                                       uint32_t addr) {
    asm volatile("ldmatrix.sync.aligned.m8n8.x4.shared.b16 {%0,%1,%2,%3}, [%4];"
                 : "=r"(r0), "=r"(r1), "=r"(r2), "=r"(r3) : "r"(addr));
}
__device__ __forceinline__ void mma16816(float* d, const uint32_t* a, const uint32_t* b) {
    asm volatile(
        "mma.sync.aligned.m16n8k16.row.col.f32.f16.f16.f32 "
        "{%0,%1,%2,%3}, {%4,%5,%6,%7}, {%8,%9}, {%0,%1,%2,%3};"
        : "+f"(d[0]), "+f"(d[1]), "+f"(d[2]), "+f"(d[3])
        : "r"(a[0]), "r"(a[1]), "r"(a[2]), "r"(a[3]), "r"(b[0]), "r"(b[1]));
}

// ---------------------------------------------------------------------------
// Kernel: embed prep — transpose, fp16+fp32 copies, 0.5||e||^2, counter reset
// ---------------------------------------------------------------------------
__global__ void k_prep_embed(const float* __restrict__ src) {
    __shared__ float Xs[32][257];
    const int t = threadIdx.x;
    const int hw0 = blockIdx.x * 32;
    const int lane = t & 31, w = t >> 5;

    #pragma unroll
    for (int i = 0; i < 32; ++i) {
        int c = w + i * 8;
        Xs[lane][c] = src[(size_t)c * 1024 + hw0 + lane];
    }
    __syncthreads();

    #pragma unroll
    for (int rr = 0; rr < 4; ++rr) {
        int r = w * 4 + rr;
        size_t ob = (size_t)(hw0 + r) * CDIM;
        #pragma unroll
        for (int j = 0; j < 8; ++j) {
            int c = lane + 32 * j;
            float x = Xs[r][c];
            g_Eh[ob + c] = __float2half_rn(x);
            g_Et[ob + c] = x;
        }
    }
    if (t < 32) {
        float s2 = 0.f;
        #pragma unroll 8
        for (int c = 0; c < CDIM; ++c) s2 = fmaf(Xs[t][c], Xs[t][c], s2);
        g_esqh[hw0 + t] = 0.5f * s2;
    }
    if (blockIdx.x == 0 && t == 0) { g_loss = 0.f; g_nrep = 0; }
}

// ---------------------------------------------------------------------------
// Kernel: input prep — transpose + fp16 convert. Grid 1024 x 256.
// ---------------------------------------------------------------------------
__global__ void k_prep_x(const float* __restrict__ src) {
    __shared__ float Xs[32][257];
    const int t = threadIdx.x;
    const int s = blockIdx.x >> 5;
    const int hw0 = (blockIdx.x & 31) * 32;
    const int lane = t & 31, w = t >> 5;
    const float* sp = src + (size_t)s * (CDIM * 1024);

    #pragma unroll
    for (int i = 0; i < 32; ++i) {
        int c = w + i * 8;
        Xs[lane][c] = sp[(size_t)c * 1024 + hw0 + lane];
    }
    __syncthreads();

    #pragma unroll
    for (int rr = 0; rr < 4; ++rr) {
        int r = w * 4 + rr;
        size_t ob = ((size_t)s * 1024 + hw0 + r) * CDIM;
        #pragma unroll
        for (int j = 0; j < 8; ++j) {
            int c = lane + 32 * j;
            g_Xh[ob + c] = __float2half_rn(Xs[r][c]);
        }
    }
}

// ---------------------------------------------------------------------------
// Kernel: fp16 HMMA GEMM + full argmin. Grid 256: one CTA per 128 positions,
// loops all 8 codeword blocks (64 chunks of BK=32, 3-stage cp.async pipeline).
// ---------------------------------------------------------------------------
#define ROWB   80
#define STG_A  (128 * ROWB)
#define STG    (2 * STG_A)
#define NCHUNK 64
#define MMA_SMEM (3 * STG)

__global__ __launch_bounds__(256, 2) void k_mma() {
    extern __shared__ char dsm[];
    const uint32_t sb = s2u(dsm);
    __shared__ float sEsq[1024];
    __shared__ float sv1[4][128];
    __shared__ float sv2[4][128];
    __shared__ int   sk1[4][128];

    const int tid = threadIdx.x;
    const int l   = tid & 31;
    const int wid = tid >> 5;
    const int wm  = wid & 1;
    const int wn  = wid >> 1;

    const int n0 = blockIdx.x * 128;

    for (int i = tid; i < 1024; i += 256) sEsq[i] = g_esqh[i];

    const __half* Ag0 = g_Xh + (size_t)n0 * CDIM;

    auto load_chunk = [&](int ci) {
        const int kb = ci >> 3, c = ci & 7;
        const __half* Ag = Ag0 + c * 32;
        const __half* Bg = g_Eh + (size_t)(kb * 128) * CDIM + c * 32;
        const uint32_t ab = sb + (ci % 3) * STG, bbs = ab + STG_A;
        #pragma unroll
        for (int u = 0; u < 2; ++u) {
            const int idx = tid + u * 256;
            const int row = idx >> 2, q = idx & 3;
            cp16(ab  + row * ROWB + q * 16, Ag + (size_t)row * CDIM + q * 8);
            cp16(bbs + row * ROWB + q * 16, Bg + (size_t)row * CDIM + q * 8);
        }
        cpcommit();
    };

    float rv1 = 3.4e38f, rv2 = 3.4e38f;
    int   rk1 = 0;

    load_chunk(0);
    load_chunk(1);
    load_chunk(2);

    #pragma unroll 1
    for (int kb = 0; kb < 8; ++kb) {
        const int k0 = kb * 128;
        float acc[4][4][4];
        #pragma unroll
        for (int i = 0; i < 4; ++i)
            #pragma unroll
            for (int j = 0; j < 4; ++j)
                #pragma unroll
                for (int r = 0; r < 4; ++r) acc[i][j][r] = 0.f;

        #pragma unroll 1
        for (int c = 0; c < 8; ++c) {
            const int ci = kb * 8 + c;
            if (ci <= NCHUNK - 3)      cpwait<2>();
            else if (ci == NCHUNK - 2) cpwait<1>();
            else                       cpwait<0>();
            __syncthreads();

            const uint32_t ab = sb + (ci % 3) * STG, bbs = ab + STG_A;
            #pragma unroll
            for (int ks = 0; ks < 2; ++ks) {
                uint32_t afr[4][4], bfr[4][2];
                #pragma unroll
                for (int mt = 0; mt < 4; ++mt)
                    ldm_x4(afr[mt][0], afr[mt][1], afr[mt][2], afr[mt][3],
                           ab + (uint32_t)(wm * 64 + mt * 16 + (l & 15)) * ROWB
                              + (uint32_t)(ks * 16 + (l >> 4) * 8) * 2);
                #pragma unroll
                for (int ntp = 0; ntp < 2; ++ntp)
                    ldm_x4(bfr[2 * ntp][0], bfr[2 * ntp][1],
                           bfr[2 * ntp + 1][0], bfr[2 * ntp + 1][1],
                           bbs + (uint32_t)(wn * 32 + ntp * 16 + ((l >> 4) & 1) * 8 + (l & 7)) * ROWB
                               + (uint32_t)(ks * 16 + ((l >> 3) & 1) * 8) * 2);
                #pragma unroll
                for (int mt = 0; mt < 4; ++mt)
                    #pragma unroll
                    for (int nt = 0; nt < 4; ++nt)
                        mma16816(acc[mt][nt], afr[mt], bfr[nt]);
            }
            __syncthreads();
            if (ci + 3 < NCHUNK) load_chunk(ci + 3);
        }

        #pragma unroll
        for (int mt = 0; mt < 4; ++mt) {
            #pragma unroll
            for (int rr = 0; rr < 2; ++rr) {
                const int rowCTA = wm * 64 + mt * 16 + (l >> 2) + rr * 8;
                float v1 = 3.4e38f, v2 = 3.4e38f;
                int   k1 = 0;
                #pragma unroll
                for (int nt = 0; nt < 4; ++nt) {
                    #pragma unroll
                    for (int cc = 0; cc < 2; ++cc) {
                        const int col = wn * 32 + nt * 8 + (l & 3) * 2 + cc;
                        const float v = sEsq[k0 + col] - acc[mt][nt][rr * 2 + cc];
                        if (v < v1)      { v2 = v1; v1 = v; k1 = k0 + col; }
                        else if (v < v2) { v2 = v; }
                    }
                }
                #pragma unroll
                for (int off = 1; off <= 2; off <<= 1) {
                    const float ov1 = __shfl_xor_sync(0xffffffffu, v1, off);
                    const float ov2 = __shfl_xor_sync(0xffffffffu, v2, off);
                    const int   ok1 = __shfl_xor_sync(0xffffffffu, k1, off);
                    if (ov1 < v1 || (ov1 == v1 && ok1 < k1)) {
                        v2 = fminf(v1, ov2); v1 = ov1; k1 = ok1;
                    } else {
                        v2 = fminf(v2, ov1);
                    }
                }
                if ((l & 3) == 0) {
                    sv1[wn][rowCTA] = v1; sv2[wn][rowCTA] = v2; sk1[wn][rowCTA] = k1;
                }
            }
        }
        __syncthreads();
        if (tid < 128) {
            #pragma unroll
            for (int w = 0; w < 4; ++w) {
                const float pv1 = sv1[w][tid], pv2 = sv2[w][tid];
                const int   pk  = sk1[w][tid];
                if (pv1 < rv1 || (pv1 == rv1 && pk < rk1)) {
                    rv2 = fminf(rv1, pv2); rv1 = pv1; rk1 = pk;
                } else {
                    rv2 = fminf(rv2, pv1);
                }
            }
        }
        __syncthreads();
    }

    if (tid < 128) {
        const int n = n0 + tid;
        g_idx[n] = rk1;
        if (rv2 - rv1 < 0.1f) {           // fp16 GEMM noise margin
            g_best[n] = 0xFFFFFFFFFFFFFFFFull;
            int slot = atomicAdd(&g_nrep, 1);
            g_rep[slot] = n;
        }
    }
}

// ---------------------------------------------------------------------------
// Kernel: exact fp32 repair, flat work grid.
// Unit = batch of 8 flagged positions; 8 warps cover all 1024 codewords
// (4 chunks of 32 per warp). Per-(warp,chunk): 8x32 dots fully in FFMA with
// float4 E streaming, warp-reduced, merged via atomicMin(packed score|k).
// ---------------------------------------------------------------------------
__global__ __launch_bounds__(256) void k_repair(const float* __restrict__ inp) {
    __shared__ float xs[8][260];
    __shared__ int   sn[8];
    const int t = threadIdx.x;
    const int w = t >> 5, lane = t & 31;
    const int nrep = g_nrep;
    const int nbatch = (nrep + 7) >> 3;

    for (int bi = blockIdx.x; bi < nbatch; bi += gridDim.x) {
        const int base = bi * 8;
        if (t < 8) sn[t] = g_rep[min(base + t, nrep - 1)];
        __syncthreads();
        for (int i = t; i < 2048; i += 256) {
            const int pp = i >> 8, c = i & 255;
            const int n = sn[pp];
            xs[pp][c] = inp[(size_t)(n >> 10) * (CDIM * 1024) + (size_t)c * 1024 + (n & 1023)];
        }
        __syncthreads();

        #pragma unroll 1
        for (int ch = 0; ch < 4; ++ch) {
            const int k = w * 128 + ch * 32 + lane;
            const float4* Ep = (const float4*)(g_Et + (size_t)k * CDIM);
            float acc[8];
            #pragma unroll
            for (int r = 0; r < 8; ++r) acc[r] = 0.f;
            #pragma unroll 8
            for (int c4 = 0; c4 < 64; ++c4) {
                const float4 e = Ep[c4];
                #pragma unroll
                for (int r = 0; r < 8; ++r) {
                    const float4 x4 = *(const float4*)&xs[r][c4 * 4];
                    acc[r] = fmaf(x4.x, e.x, acc[r]);
                    acc[r] = fmaf(x4.y, e.y, acc[r]);
                    acc[r] = fmaf(x4.z, e.z, acc[r]);
                    acc[r] = fmaf(x4.w, e.w, acc[r]);
                }
            }
            const float eh = g_esqh[k];
            #pragma unroll
            for (int r = 0; r < 8; ++r) {
                const float v = eh - acc[r];
                uint32_t u = __float_as_uint(v);
                u ^= (u & 0x80000000u) ? 0xFFFFFFFFu : 0x80000000u;
                unsigned long long key = ((unsigned long long)u << 32) | (uint32_t)k;
                #pragma unroll
                for (int off = 16; off; off >>= 1) {
                    const unsigned long long o = __shfl_xor_sync(0xffffffffu, key, off);
                    key = min(key, o);
                }
                if (lane == 0) atomicMin(&g_best[sn[r]], key);
            }
        }
        __syncthreads();
    }
}

// ---------------------------------------------------------------------------
// Kernel: unpack repaired indices
// ---------------------------------------------------------------------------
__global__ void k_repfin() {
    const int nrep = g_nrep;
    for (int i = blockIdx.x * 256 + threadIdx.x; i < nrep; i += gridDim.x * 256) {
        const int n = g_rep[i];
        g_idx[n] = (int)(g_best[n] & 0xFFFFFFFFull);
    }
}

// ---------------------------------------------------------------------------
// Kernel: quantize gather + loss (32 positions/block, smem-staged rows)
// ---------------------------------------------------------------------------
__global__ __launch_bounds__(256) void k_quant(const float* __restrict__ inp,
                                               float* __restrict__ outq) {
    __shared__ float eq[32][257];
    __shared__ int   sidx[32];
    const int t  = threadIdx.x;
    const int n0 = blockIdx.x * 32;
    const int b  = n0 >> 10;
    const int hw0 = n0 & 1023;

    if (t < 32) sidx[t] = g_idx[n0 + t];
    __syncthreads();
    #pragma unroll 1
    for (int j = 0; j < 32; ++j) {
        eq[j][t] = g_Et[(size_t)sidx[j] * CDIM + t];
    }
    __syncthreads();

    const int hw_l = t & 31;
    const int cg   = t >> 5;
    const size_t base = (size_t)b * (CDIM * 1024) + hw0 + hw_l;

    float ls = 0.f;
    #pragma unroll 4
    for (int cb = 0; cb < 32; ++cb) {
        const int c = cb * 8 + cg;
        const size_t a = base + (size_t)c * 1024;
        const float x = inp[a];
        const float e = eq[hw_l][c];
        outq[a] = e;
        const float d = e - x;
        ls = fmaf(d, d, ls);
    }

    __shared__ float red[256];
    red[t] = ls;
    __syncthreads();
    #pragma unroll
    for (int s = 128; s; s >>= 1) {
        if (t < s) red[t] += red[t + s];
        __syncthreads();
    }
    if (t == 0) atomicAdd(&g_loss, red[0]);
}

// ---------------------------------------------------------------------------
// Kernel: onehot + loss scalar
// ---------------------------------------------------------------------------
__global__ void k_onehot(float* __restrict__ d_out) {
    float* oh = d_out + (QELEMS + 1);
    const int t  = threadIdx.x;
    const int r0 = blockIdx.x * 8;
    #pragma unroll
    for (int rr = 0; rr < 8; ++rr) {
        const int n   = r0 + rr;
        const int idx = g_idx[n];
        const size_t base = (size_t)n * KEMB;
        #pragma unroll
        for (int p = 0; p < 4; ++p) {
            const int j = t + p * 256;
            oh[base + j] = (j == idx) ? 1.0f : 0.0f;
        }
    }
    if (blockIdx.x == 0 && t == 0) {
        d_out[QELEMS] = 1.25f * g_loss / (float)QELEMS;
    }
}

// ---------------------------------------------------------------------------
extern "C" void kernel_launch(void* const* d_in, const int* in_sizes, int n_in,
                              void* d_out, int out_size) {
    const float* inp = (const float*)d_in[0];
    const float* emb = (const float*)d_in[1];
    float* out = (float*)d_out;

    cudaFuncSetAttribute(k_mma, cudaFuncAttributeMaxDynamicSharedMemorySize, MMA_SMEM);

    k_prep_embed<<<32, 256>>>(emb);
    k_prep_x<<<1024, 256>>>(inp);
    k_mma<<<256, 256, MMA_SMEM>>>();
    k_repair<<<296, 256>>>(inp);
    k_repfin<<<32, 256>>>();
    k_quant<<<1024, 256>>>(inp, out);
    k_onehot<<<4096, 256>>>(out);
}